// round 12
// baseline (speedup 1.0000x reference)
#include <cuda_runtime.h>
#include <cuda_fp16.h>
#include <cstdint>
#include <cstddef>

// ---------------- problem constants ----------------
#define TSTEPS 256
#define BB 128      // batch
#define HH 512      // GRU hidden
#define LL 1024     // LSTM hidden
#define VV 1024     // vocab

// ---------------- config (PBK=128 slabs, 2-buffer cp.async ring) ----------------
#define NTH 512
#define BM 128
#define PBK 128
#define ASTRH (PBK + 8)             // 136 halfs (272B row: ldmatrix conflict-free)
#define WSTRH_G (HH + 8)            // 520 halfs
#define WSTRH_L (LL + 8)            // 1032 halfs
#define CSTR 68                     // fp32 staging stride
#define NBUF 2
#define ABUF_B (BM * ASTRH * 2)     // 34816 bytes per A buffer
#define BBUF_B (64 * ASTRH * 2)     // 17408 bytes per FC-B buffer

// dynamic smem (bytes):
//  GRU : 64*WSTRH_G*2  + 2*ABUF_B = 66560 + 69632  = 136192
//  XG  : 128*WSTRH_G*2 + 2*ABUF_B = 133120 + 69632 = 202752
//  LSTM: 64*WSTRH_L*2  + 2*ABUF_B = 132096 + 69632 = 201728
//  FC  : 2*BBUF_B      + 2*ABUF_B = 34816 + 69632  = 104448
#define SMEM_FUSED 202752
#define F_ATILE (NBUF * 64 * ASTRH)  // FC As offset (halfs)

// ---------------- persistent device scratch ----------------
__device__ __align__(256) __half g_Wgh  [2048 * 512];
__device__ __align__(256) __half g_Wg1h [2048 * 512];
__device__ __align__(256) float  g_bg   [2048];
__device__ __align__(256) __half g_Wihlh[4096 * 512];
__device__ __align__(256) float  g_bl   [4096];
__device__ __align__(256) __half g_Whhlh[4096 * 1024];
__device__ __align__(256) __half g_fcWh [1024 * 1024];
__device__ __align__(256) float  g_x    [2 * BB * HH];
__device__ __align__(256) __half g_xh   [2 * BB * HH];
__device__ __align__(256) __half g_zh   [BB * HH];
__device__ __align__(256) __half g_seqh [TSTEPS * BB * HH];
__device__ __align__(256) float  g_Xg   [(size_t)TSTEPS * BB * 4096];
__device__ __align__(256) __half g_hh   [2 * BB * LL];
__device__ __align__(256) float  g_c    [BB * LL];
__device__ __align__(256) __half g_hsh  [(size_t)TSTEPS * BB * LL];
__device__ __align__(128) unsigned g_bar_gru[32];
__device__ __align__(128) unsigned g_bar_xg[32];
__device__ __align__(128) unsigned g_bar_lstm[32];
__device__ __align__(128) unsigned g_fc_cnt[32];

// ---------------- helpers ----------------
__device__ __forceinline__ void mma_f16(float4& d,
                                        uint32_t a0, uint32_t a1, uint32_t a2, uint32_t a3,
                                        uint32_t b0, uint32_t b1) {
    asm volatile(
        "mma.sync.aligned.m16n8k16.row.col.f32.f16.f16.f32 "
        "{%0,%1,%2,%3}, {%4,%5,%6,%7}, {%8,%9}, {%0,%1,%2,%3};\n"
        : "+f"(d.x), "+f"(d.y), "+f"(d.z), "+f"(d.w)
        : "r"(a0), "r"(a1), "r"(a2), "r"(a3), "r"(b0), "r"(b1));
}

__device__ __forceinline__ void ldsm_x4(uint32_t& r0, uint32_t& r1, uint32_t& r2, uint32_t& r3,
                                        uint32_t addr) {
    asm volatile("ldmatrix.sync.aligned.m8n8.x4.shared.b16 {%0,%1,%2,%3}, [%4];"
                 : "=r"(r0), "=r"(r1), "=r"(r2), "=r"(r3) : "r"(addr));
}
__device__ __forceinline__ void ldsm_x2(uint32_t& r0, uint32_t& r1, uint32_t addr) {
    asm volatile("ldmatrix.sync.aligned.m8n8.x2.shared.b16 {%0,%1}, [%2];"
                 : "=r"(r0), "=r"(r1) : "r"(addr));
}

__device__ __forceinline__ void cpa16(uint32_t dst, const __half* src) {
    asm volatile("cp.async.cg.shared.global [%0], [%1], 16;" :: "r"(dst), "l"(src));
}
#define CP_COMMIT() asm volatile("cp.async.commit_group;" ::: "memory")
#define CP_WAIT0()  asm volatile("cp.async.wait_group 0;"  ::: "memory")

__device__ __forceinline__ float sigf(float x) { return 1.0f / (1.0f + expf(-x)); }

__device__ __forceinline__ void bar_arrive(unsigned* bar) {
    __syncthreads();
    if (threadIdx.x == 0)
        asm volatile("red.release.gpu.global.add.u32 [%0], 1;" :: "l"(bar) : "memory");
}
__device__ __forceinline__ void wait_ge(unsigned* bar, unsigned target) {
    if (threadIdx.x == 0) {
        unsigned v;
        do {
            asm volatile("ld.acquire.gpu.global.b32 %0, [%1];" : "=r"(v) : "l"(bar));
        } while (v < target);
    }
    __syncthreads();
}
__device__ __forceinline__ void wait_ge2(unsigned* barA, unsigned tA,
                                         unsigned* barB, unsigned tB) {
    if (threadIdx.x == 0) {
        unsigned va, vb;
        do {
            asm volatile("ld.acquire.gpu.global.b32 %0, [%1];" : "=r"(va) : "l"(barA));
            asm volatile("ld.acquire.gpu.global.b32 %0, [%1];" : "=r"(vb) : "l"(barB));
        } while (va < tA || vb < tB);
    }
    __syncthreads();
}

// lane offsets (bytes) for ldmatrix source addresses
__device__ __forceinline__ uint32_t a_lane_off(int lane) {
    const int am = lane >> 3;
    return (uint32_t)((((am & 1) * 8 + (lane & 7)) * ASTRH) * 2 + (am >> 1) * 16);
}
__device__ __forceinline__ uint32_t b_lane_off(int lane, int wstr) {
    return (uint32_t)(((lane & 7) * wstr) * 2 + ((lane >> 3) & 1) * 16);
}

// issue one A slab (128 rows x 128 halfs): 4 threads/row, 4 x 16B per thread
__device__ __forceinline__ void a_issue(uint32_t buf_b, const __half* __restrict__ A,
                                        int ldK, int k0, int tid) {
    const int r = tid >> 2, c4 = (tid & 3) * 8;
    const __half* src = A + (size_t)r * ldK + k0 + c4;
    const uint32_t dst = buf_b + (uint32_t)((r * ASTRH + c4) * 2);
#pragma unroll
    for (int j = 0; j < 4; j++)
        cpa16(dst + j * 64, src + j * 32);
}
// issue one FC B slab (64 rows x 128 halfs): 8 threads/row, 2 x 16B per thread
__device__ __forceinline__ void b_issue(uint32_t buf_b, const __half* __restrict__ W,
                                        int ldK, int k0, int tid) {
    const int r = tid >> 3, c8 = (tid & 7) * 8;
    const __half* src = W + (size_t)r * ldK + k0 + c8;
    const uint32_t dst = buf_b + (uint32_t)((r * ASTRH + c8) * 2);
#pragma unroll
    for (int j = 0; j < 2; j++)
        cpa16(dst + j * 128, src + j * 64);
}

// one PBK=128 k-slab via ldmatrix (8 kk iters)
template <int NI>
__device__ __forceinline__ void do_kk8(uint32_t AcB, uint32_t WsB, int wstr,
                                       uint32_t alo, uint32_t blo,
                                       int wm, int wn, float4 (&acc)[2][NI]) {
#pragma unroll
    for (int kk = 0; kk < 8; kk++) {
        uint32_t af[2][4];
#pragma unroll
        for (int mi = 0; mi < 2; mi++) {
            const uint32_t aaddr = AcB + (uint32_t)(((wm * 32 + mi * 16) * ASTRH + kk * 16) * 2) + alo;
            ldsm_x4(af[mi][0], af[mi][1], af[mi][2], af[mi][3], aaddr);
        }
#pragma unroll
        for (int ni = 0; ni < NI; ni++) {
            const uint32_t baddr = WsB + (uint32_t)(((wn * (NI * 8) + ni * 8) * wstr + kk * 16) * 2) + blo;
            uint32_t b0, b1;
            ldsm_x2(b0, b1, baddr);
#pragma unroll
            for (int mi = 0; mi < 2; mi++)
                mma_f16(acc[mi][ni], af[mi][0], af[mi][1], af[mi][2], af[mi][3], b0, b1);
        }
    }
}

// generic chain mainloop: NK slabs of A against resident weights, NBUF=2 ring.
// Order per slab: wait(buf cur) -> sync (all warps done reading buf cur^1) ->
// issue next into buf cur^1 -> compute buf cur. Race-free by construction.
template <int NI>
__device__ __forceinline__ void chain_mainloop(int NK, const __half* __restrict__ Abh,
                                               int ldK, uint32_t as_u32, uint32_t ws_u32,
                                               int wstr, uint32_t alo, uint32_t blo,
                                               int wm, int wn, int tid,
                                               float4 (&acc)[2][NI]) {
    a_issue(as_u32, Abh, ldK, 0, tid);
    CP_COMMIT();
    for (int kt = 0; kt < NK; ++kt) {
        const int cur = kt & 1;
        CP_WAIT0();
        __syncthreads();
        if (kt + 1 < NK) {
            a_issue(as_u32 + (cur ^ 1) * ABUF_B, Abh, ldK, (kt + 1) * PBK, tid);
            CP_COMMIT();
        }
        do_kk8<NI>(as_u32 + cur * ABUF_B, ws_u32 + kt * PBK * 2, wstr,
                   alo, blo, wm, wn, acc);
    }
    __syncthreads();   // protect As ring reuse as Cs staging
}

// ============================================================================
// FC work-steal: logits tile [128 x 64] = hs_t @ fcW^T + fcb (A+B ring)
// ============================================================================
__device__ void fc_worker(uint32_t smb, const float* __restrict__ fcb,
                          float* __restrict__ out) {
    __shared__ int s_tile;
    const uint32_t bs_u32 = smb;                    // 2 x [64][ASTRH]
    const uint32_t as_u32 = smb + F_ATILE * 2;      // 2 x [128][ASTRH]

    const int tid  = threadIdx.x;
    const int lane = tid & 31;
    const int wid  = tid >> 5;
    const int wm   = wid & 3;
    const int wn   = wid >> 2;
    const uint32_t alo = a_lane_off(lane);
    const uint32_t blo = b_lane_off(lane, ASTRH);

    while (true) {
        __syncthreads();
        if (tid == 0) s_tile = (int)atomicAdd(&g_fc_cnt[0], 1u);
        __syncthreads();
        const int tile = s_tile;
        if (tile >= TSTEPS * 16) return;
        const int t  = tile >> 4;
        const int n0 = (tile & 15) * 64;
        wait_ge(g_bar_lstm, 64u * (unsigned)(t + 1));

        const __half* Abh = g_hsh  + (size_t)t * BB * LL;
        const __half* Wb  = g_fcWh + (size_t)n0 * LL;

        float4 acc[2][2];
#pragma unroll
        for (int mi = 0; mi < 2; mi++)
#pragma unroll
            for (int ni = 0; ni < 2; ni++) acc[mi][ni] = make_float4(0.f, 0.f, 0.f, 0.f);

        a_issue(as_u32, Abh, LL, 0, tid);
        b_issue(bs_u32, Wb,  LL, 0, tid);
        CP_COMMIT();
        for (int kt = 0; kt < 8; ++kt) {
            const int cur = kt & 1;
            CP_WAIT0();
            __syncthreads();
            if (kt + 1 < 8) {
                a_issue(as_u32 + (cur ^ 1) * ABUF_B, Abh, LL, (kt + 1) * PBK, tid);
                b_issue(bs_u32 + (cur ^ 1) * BBUF_B, Wb,  LL, (kt + 1) * PBK, tid);
                CP_COMMIT();
            }
            do_kk8<2>(as_u32 + cur * ABUF_B, bs_u32 + cur * BBUF_B, ASTRH,
                      alo, blo, wm, wn, acc);
        }

#pragma unroll
        for (int mi = 0; mi < 2; mi++) {
#pragma unroll
            for (int ni = 0; ni < 2; ni++) {
                const int r   = wm * 32 + mi * 16 + (lane >> 2);
                const int col = n0 + wn * 16 + ni * 8 + 2 * (lane & 3);
                const float b0 = fcb[col], b1 = fcb[col + 1];
                float* o0 = out + ((size_t)r * TSTEPS + t) * VV + col;
                float* o1 = out + ((size_t)(r + 8) * TSTEPS + t) * VV + col;
                *(float2*)o0 = make_float2(acc[mi][ni].x + b0, acc[mi][ni].y + b1);
                *(float2*)o1 = make_float2(acc[mi][ni].z + b0, acc[mi][ni].w + b1);
            }
        }
    }
}

// ============================================================================
// Fused pipelined kernel, grid = 148 (512 thr = 16 warps/SM):
//   bid 0-31: GRU (64 cols) | bid 32-63: XG (128 cols) | bid 64-127: LSTM (64 cols)
//   bid 128-147: FC steal (chain CTAs join at the end)
// ============================================================================
__global__ void __launch_bounds__(NTH)
fused_persist(const float* __restrict__ z, const float* __restrict__ fcb,
              float* __restrict__ out) {
    extern __shared__ __half smh[];
    const uint32_t smb = (uint32_t)__cvta_generic_to_shared(smh);
    const int tid  = threadIdx.x;
    const int lane = tid & 31;
    const int wid  = tid >> 5;
    const int wm   = wid & 3;
    const int wn   = wid >> 2;
    const int bid  = blockIdx.x;
    const uint32_t alo = a_lane_off(lane);

    if (bid < 32) {
        // ================= GRU chain: 64 cols =================
        __half* Ws = smh;                               // [64][WSTRH_G]
        const uint32_t ws_u32 = smb;
        const uint32_t as_u32 = smb + 64 * WSTRH_G * 2; // 2 x [128][ASTRH]
        float* Cs = (float*)(smh + 64 * WSTRH_G);       // staging, stride CSTR
        const uint32_t blo = b_lane_off(lane, WSTRH_G);
        const int n0 = bid * 64;

        for (int i = tid; i < 64 * 64; i += NTH) {
            const int r = i >> 6, c = (i & 63) * 8;
            *(uint4*)(Ws + r * WSTRH_G + c) = *(const uint4*)(g_Wg1h + (size_t)(n0 + r) * HH + c);
        }
        __syncthreads();

        for (int t = 1; t < TSTEPS; ++t) {
            const __half* Abh  = (t == 1) ? g_zh : g_xh + (size_t)((t - 1) & 1) * BB * HH;
            const float*  hp32 = (t == 1) ? z    : g_x  + (size_t)((t - 1) & 1) * BB * HH;
            float*  xo32 = g_x    + (size_t)(t & 1) * BB * HH;
            __half* xoh  = g_xh   + (size_t)(t & 1) * BB * HH;
            __half* so   = g_seqh + (size_t)t * BB * HH;

            float hp[4];
#pragma unroll
            for (int s = 0; s < 4; s++) {
                const int it = tid + s * NTH;
                hp[s] = hp32[(size_t)(it >> 4) * HH + (n0 >> 2) + (it & 15)];
            }

            float4 acc[2][2];
#pragma unroll
            for (int mi = 0; mi < 2; mi++)
#pragma unroll
                for (int ni = 0; ni < 2; ni++) acc[mi][ni] = make_float4(0.f, 0.f, 0.f, 0.f);

            chain_mainloop<2>(4, Abh, HH, as_u32, ws_u32, WSTRH_G,
                              alo, blo, wm, wn, tid, acc);

#pragma unroll
            for (int mi = 0; mi < 2; mi++) {
#pragma unroll
                for (int ni = 0; ni < 2; ni++) {
                    const int r = wm * 32 + mi * 16 + (lane >> 2);
                    const int c = wn * 16 + ni * 8 + 2 * (lane & 3);
                    const float b0 = g_bg[n0 + c], b1 = g_bg[n0 + c + 1];
                    Cs[r * CSTR + c]           = acc[mi][ni].x + b0;
                    Cs[r * CSTR + c + 1]       = acc[mi][ni].y + b1;
                    Cs[(r + 8) * CSTR + c]     = acc[mi][ni].z + b0;
                    Cs[(r + 8) * CSTR + c + 1] = acc[mi][ni].w + b1;
                }
            }
            __syncthreads();

#pragma unroll
            for (int s = 0; s < 4; s++) {
                const int it  = tid + s * NTH;
                const int u   = it & 15;
                const int row = it >> 4;
                const int jg  = (n0 >> 2) + u;
                const float4 cv = *(const float4*)(Cs + row * CSTR + 4 * u);
                const float rg = sigf(cv.x);
                const float zg = sigf(cv.y);
                const float nn = tanhf(cv.z + rg * cv.w);
                const float xn = (1.f - zg) * nn + zg * hp[s];
                const int oi = row * HH + jg;
                xo32[oi] = xn;
                xoh[oi]  = __float2half_rn(xn);
                so[oi]   = __float2half_rn(fmaxf(xn, 0.f));
            }

            bar_arrive(g_bar_gru);
            if (t < TSTEPS - 1) {
                wait_ge(g_bar_gru, 32u * (unsigned)t);
                if (t == 1) {
                    for (int i = tid; i < 64 * 64; i += NTH) {
                        const int r = i >> 6, c = (i & 63) * 8;
                        *(uint4*)(Ws + r * WSTRH_G + c) =
                            *(const uint4*)(g_Wgh + (size_t)(n0 + r) * HH + c);
                    }
                    __syncthreads();
                }
            }
        }
        fc_worker(smb, fcb, out);

    } else if (bid < 64) {
        // ================= XG: 128 cols =================
        __half* Ws = smh;                                // [128][WSTRH_G]
        const uint32_t ws_u32 = smb;
        const uint32_t as_u32 = smb + 128 * WSTRH_G * 2;
        const uint32_t blo = b_lane_off(lane, WSTRH_G);
        const int n0 = (bid - 32) * 128;

        for (int i = tid; i < 128 * 64; i += NTH) {
            const int r = i >> 6, c = (i & 63) * 8;
            *(uint4*)(Ws + r * WSTRH_G + c) = *(const uint4*)(g_Wihlh + (size_t)(n0 + r) * HH + c);
        }
        __syncthreads();

        for (int t = 1; t < TSTEPS; ++t) {
            wait_ge(g_bar_gru, 32u * (unsigned)t);
            const __half* Abh = g_seqh + (size_t)t * BB * HH;

            float4 acc[2][4];
#pragma unroll
            for (int mi = 0; mi < 2; mi++)
#pragma unroll
                for (int ni = 0; ni < 4; ni++) acc[mi][ni] = make_float4(0.f, 0.f, 0.f, 0.f);

            chain_mainloop<4>(4, Abh, HH, as_u32, ws_u32, WSTRH_G,
                              alo, blo, wm, wn, tid, acc);

#pragma unroll
            for (int mi = 0; mi < 2; mi++) {
#pragma unroll
                for (int ni = 0; ni < 4; ni++) {
                    const int r   = wm * 32 + mi * 16 + (lane >> 2);
                    const int col = n0 + wn * 32 + ni * 8 + 2 * (lane & 3);
                    const float b0 = g_bl[col], b1 = g_bl[col + 1];
                    float* o0 = g_Xg + ((size_t)t * BB + r) * 4096 + col;
                    float* o1 = g_Xg + ((size_t)t * BB + r + 8) * 4096 + col;
                    *(float2*)o0 = make_float2(acc[mi][ni].x + b0, acc[mi][ni].y + b1);
                    *(float2*)o1 = make_float2(acc[mi][ni].z + b0, acc[mi][ni].w + b1);
                }
            }
            bar_arrive(g_bar_xg);
        }
        fc_worker(smb, fcb, out);

    } else if (bid < 128) {
        // ================= LSTM chain: 64 cols =================
        __half* Ws = smh;                                // [64][WSTRH_L]
        const uint32_t ws_u32 = smb;
        const uint32_t as_u32 = smb + 64 * WSTRH_L * 2;
        float* Cs = (float*)(smh + 64 * WSTRH_L);        // staging, stride CSTR
        const uint32_t blo = b_lane_off(lane, WSTRH_L);
        const int n0 = (bid - 64) * 64;

        for (int i = tid; i < 64 * 128; i += NTH) {
            const int r = i >> 7, c = (i & 127) * 8;
            *(uint4*)(Ws + r * WSTRH_L + c) = *(const uint4*)(g_Whhlh + (size_t)(n0 + r) * LL + c);
        }
        __syncthreads();

        for (int t = 0; t < TSTEPS; ++t) {
            if (t >= 1)
                wait_ge2(g_bar_xg, 32u * (unsigned)t, g_bar_lstm, 64u * (unsigned)t);

            const __half* Abh = g_hh + (size_t)(t & 1) * BB * LL;
            __half* hoh       = g_hh + (size_t)((t + 1) & 1) * BB * LL;

            float4 xg[4];
            float  cc[4];
#pragma unroll
            for (int s = 0; s < 4; s++) {
                const int it  = tid + s * NTH;
                const int row = it >> 4;
                const int u   = it & 15;
                xg[s] = *(const float4*)(g_Xg + ((size_t)t * BB + row) * 4096 + n0 + 4 * u);
                cc[s] = g_c[row * LL + (n0 >> 2) + u];
            }

            float4 acc[2][2];
#pragma unroll
            for (int mi = 0; mi < 2; mi++)
#pragma unroll
                for (int ni = 0; ni < 2; ni++) acc[mi][ni] = make_float4(0.f, 0.f, 0.f, 0.f);

            if (t >= 1)
                chain_mainloop<2>(8, Abh, LL, as_u32, ws_u32, WSTRH_L,
                                  alo, blo, wm, wn, tid, acc);

#pragma unroll
            for (int mi = 0; mi < 2; mi++) {
#pragma unroll
                for (int ni = 0; ni < 2; ni++) {
                    const int r = wm * 32 + mi * 16 + (lane >> 2);
                    const int c = wn * 16 + ni * 8 + 2 * (lane & 3);
                    Cs[r * CSTR + c]           = acc[mi][ni].x;
                    Cs[r * CSTR + c + 1]       = acc[mi][ni].y;
                    Cs[(r + 8) * CSTR + c]     = acc[mi][ni].z;
                    Cs[(r + 8) * CSTR + c + 1] = acc[mi][ni].w;
                }
            }
            __syncthreads();

#pragma unroll
            for (int s = 0; s < 4; s++) {
                const int it  = tid + s * NTH;
                const int u   = it & 15;
                const int row = it >> 4;
                const int jg  = (n0 >> 2) + u;
                const float4 cv = *(const float4*)(Cs + row * CSTR + 4 * u);
                const float ig = sigf(cv.x + xg[s].x);
                const float fg = sigf(cv.y + xg[s].y);
                const float gg = tanhf(cv.z + xg[s].z);
                const float og = sigf(cv.w + xg[s].w);
                const int ci = row * LL + jg;
                const float cn = fg * cc[s] + ig * gg;
                g_c[ci] = cn;
                const float hn = og * tanhf(cn);
                hoh[ci] = __float2half_rn(hn);
                g_hsh[((size_t)t * BB + row) * LL + jg] = __float2half_rn(hn);
            }

            bar_arrive(g_bar_lstm);
        }
        fc_worker(smb, fcb, out);

    } else {
        fc_worker(smb, fcb, out);
    }
}

// ---------------- prep kernels ----------------
__global__ void prep_gru(const float* __restrict__ Wih, const float* __restrict__ Whh,
                         const float* __restrict__ bih, const float* __restrict__ bhh) {
    const int idx = blockIdx.x * blockDim.x + threadIdx.x;
    if (idx < 2048 * 512) {
        const int row = idx >> 9, k = idx & 511;
        const int j = row >> 2, g = row & 3;
        float wg, w1;
        if (g == 0)      { wg = Wih[j * 512 + k] + Whh[j * 512 + k];                 w1 = Whh[j * 512 + k]; }
        else if (g == 1) { wg = Wih[(512 + j) * 512 + k] + Whh[(512 + j) * 512 + k]; w1 = Whh[(512 + j) * 512 + k]; }
        else if (g == 2) { wg = Wih[(1024 + j) * 512 + k];                           w1 = 0.f; }
        else             { wg = Whh[(1024 + j) * 512 + k];                           w1 = wg; }
        g_Wgh[idx]  = __float2half_rn(wg);
        g_Wg1h[idx] = __float2half_rn(w1);
    }
    if (idx < 2048) {
        const int j = idx >> 2, g = idx & 3;
        float b;
        if (g == 0)      b = bih[j] + bhh[j];
        else if (g == 1) b = bih[512 + j] + bhh[512 + j];
        else if (g == 2) b = bih[1024 + j];
        else             b = bhh[1024 + j];
        g_bg[idx] = b;
    }
}

__global__ void prep_lstm(const float* __restrict__ Wih, const float* __restrict__ Whh,
                          const float* __restrict__ bih, const float* __restrict__ bhh,
                          const float* __restrict__ fcW) {
    const int idx = blockIdx.x * blockDim.x + threadIdx.x;
    if (idx < 4096 * 1024) {
        const int row = idx >> 10, k = idx & 1023;
        const int j = row >> 2, p = row & 3;
        g_Whhlh[idx] = __float2half_rn(Whh[(size_t)(p * 1024 + j) * 1024 + k]);
    }
    if (idx < 4096 * 512) {
        const int row = idx >> 9, k = idx & 511;
        const int j = row >> 2, p = row & 3;
        g_Wihlh[idx] = __float2half_rn(Wih[(size_t)(p * 1024 + j) * 512 + k]);
    }
    if (idx < 1024 * 1024) {
        g_fcWh[idx] = __float2half_rn(fcW[idx]);
    }
    if (idx < 4096) {
        const int j = idx >> 2, p = idx & 3;
        g_bl[idx] = bih[p * 1024 + j] + bhh[p * 1024 + j];
    }
}

__global__ void prep_zero(const float* __restrict__ z) {
    const int idx = blockIdx.x * blockDim.x + threadIdx.x;
    if (idx < BB * LL) { g_hh[idx] = __float2half_rn(0.f); g_c[idx] = 0.f; }
    if (idx < BB * HH) { g_zh[idx] = __float2half_rn(z[idx]); }
    if (idx < BB * 4096) { g_Xg[idx] = g_bl[idx & 4095]; }
    if (idx == 0) { g_bar_gru[0] = 0u; g_bar_xg[0] = 0u; g_bar_lstm[0] = 0u; g_fc_cnt[0] = 0u; }
}

// ---------------- host launcher ----------------
extern "C" void kernel_launch(void* const* d_in, const int* in_sizes, int n_in,
                              void* d_out, int out_size) {
    const float* z    = (const float*)d_in[0];
    const float* gWih = (const float*)d_in[2];
    const float* gWhh = (const float*)d_in[3];
    const float* gbih = (const float*)d_in[4];
    const float* gbhh = (const float*)d_in[5];
    const float* lWih = (const float*)d_in[6];
    const float* lWhh = (const float*)d_in[7];
    const float* lbih = (const float*)d_in[8];
    const float* lbhh = (const float*)d_in[9];
    const float* fcW  = (const float*)d_in[10];
    const float* fcb  = (const float*)d_in[11];
    float* out = (float*)d_out;

    cudaFuncSetAttribute(fused_persist, cudaFuncAttributeMaxDynamicSharedMemorySize, SMEM_FUSED);

    prep_gru <<<(2048 * 512 + 255) / 256, 256>>>(gWih, gWhh, gbih, gbhh);
    prep_lstm<<<(4096 * 1024 + 255) / 256, 256>>>(lWih, lWhh, lbih, lbhh, fcW);
    prep_zero<<<(BB * 4096 + 255) / 256, 256>>>(z);

    // fused pipeline: GRU | XG | LSTM | FC on disjoint CTA sets,
    // PBK=128 slabs halve the per-step sync count; NBUF=2 cp.async ring
    fused_persist<<<148, NTH, SMEM_FUSED>>>(z, fcb, out);
}

// round 14
// speedup vs baseline: 1.0832x; 1.0832x over previous
#include <cuda_runtime.h>
#include <cuda_fp16.h>
#include <cstdint>
#include <cstddef>

// ---------------- problem constants ----------------
#define TSTEPS 256
#define BB 128      // batch
#define HH 512      // GRU hidden
#define LL 1024     // LSTM hidden
#define VV 1024     // vocab

// ---------------- config (R11 base + k-split warp tiling in chains) ----------------
#define NTH 512
#define BM 128
#define PBK 64
#define ASTRH (PBK + 8)             // 72 halfs (144B row: ldmatrix conflict-free)
#define WSTRH_G (HH + 8)            // 520 halfs
#define WSTRH_L (LL + 8)            // 1032 halfs
#define CSTR 68                     // fp32 staging stride (64-col tiles)
#define CSTRX 132                   // fp32 staging stride (128-col XG tile)
#define NBUF 4
#define ABUF_B (BM * ASTRH * 2)     // 18432 bytes per A buffer
#define BBUF_B (64 * ASTRH * 2)     // 9216 bytes per FC-B buffer

#define SMEM_FUSED 206848
#define F_ATILE (NBUF * 64 * ASTRH)  // FC As offset (halfs)

// ---------------- persistent device scratch ----------------
__device__ __align__(256) __half g_Wgh  [2048 * 512];
__device__ __align__(256) __half g_Wg1h [2048 * 512];
__device__ __align__(256) float  g_bg   [2048];
__device__ __align__(256) __half g_Wihlh[4096 * 512];
__device__ __align__(256) float  g_bl   [4096];
__device__ __align__(256) __half g_Whhlh[4096 * 1024];
__device__ __align__(256) __half g_fcWh [1024 * 1024];
__device__ __align__(256) float  g_x    [2 * BB * HH];
__device__ __align__(256) __half g_xh   [2 * BB * HH];
__device__ __align__(256) __half g_zh   [BB * HH];
__device__ __align__(256) __half g_seqh [TSTEPS * BB * HH];
__device__ __align__(256) float  g_Xg   [(size_t)TSTEPS * BB * 4096];
__device__ __align__(256) __half g_hh   [2 * BB * LL];
__device__ __align__(256) float  g_c    [BB * LL];
__device__ __align__(256) __half g_hsh  [(size_t)TSTEPS * BB * LL];
__device__ __align__(128) unsigned g_bar_gru[32];
__device__ __align__(128) unsigned g_bar_xg[32];
__device__ __align__(128) unsigned g_bar_lstm[32];
__device__ __align__(128) unsigned g_fc_cnt[32];

// ---------------- helpers ----------------
__device__ __forceinline__ void mma_f16(float4& d,
                                        uint32_t a0, uint32_t a1, uint32_t a2, uint32_t a3,
                                        uint32_t b0, uint32_t b1) {
    asm volatile(
        "mma.sync.aligned.m16n8k16.row.col.f32.f16.f16.f32 "
        "{%0,%1,%2,%3}, {%4,%5,%6,%7}, {%8,%9}, {%0,%1,%2,%3};\n"
        : "+f"(d.x), "+f"(d.y), "+f"(d.z), "+f"(d.w)
        : "r"(a0), "r"(a1), "r"(a2), "r"(a3), "r"(b0), "r"(b1));
}

__device__ __forceinline__ void ldsm_x4(uint32_t& r0, uint32_t& r1, uint32_t& r2, uint32_t& r3,
                                        uint32_t addr) {
    asm volatile("ldmatrix.sync.aligned.m8n8.x4.shared.b16 {%0,%1,%2,%3}, [%4];"
                 : "=r"(r0), "=r"(r1), "=r"(r2), "=r"(r3) : "r"(addr));
}
__device__ __forceinline__ void ldsm_x2(uint32_t& r0, uint32_t& r1, uint32_t addr) {
    asm volatile("ldmatrix.sync.aligned.m8n8.x2.shared.b16 {%0,%1}, [%2];"
                 : "=r"(r0), "=r"(r1) : "r"(addr));
}

__device__ __forceinline__ void cpa16(uint32_t dst, const __half* src) {
    asm volatile("cp.async.cg.shared.global [%0], [%1], 16;" :: "r"(dst), "l"(src));
}
#define CP_COMMIT() asm volatile("cp.async.commit_group;" ::: "memory")
#define CP_WAIT2()  asm volatile("cp.async.wait_group 2;"  ::: "memory")

__device__ __forceinline__ float sigf(float x) { return 1.0f / (1.0f + expf(-x)); }

__device__ __forceinline__ void bar_arrive(unsigned* bar) {
    __syncthreads();
    if (threadIdx.x == 0)
        asm volatile("red.release.gpu.global.add.u32 [%0], 1;" :: "l"(bar) : "memory");
}
__device__ __forceinline__ void wait_ge(unsigned* bar, unsigned target) {
    if (threadIdx.x == 0) {
        unsigned v;
        do {
            asm volatile("ld.acquire.gpu.global.b32 %0, [%1];" : "=r"(v) : "l"(bar));
        } while (v < target);
    }
    __syncthreads();
}
__device__ __forceinline__ void wait_ge2(unsigned* barA, unsigned tA,
                                         unsigned* barB, unsigned tB) {
    if (threadIdx.x == 0) {
        unsigned va, vb;
        do {
            asm volatile("ld.acquire.gpu.global.b32 %0, [%1];" : "=r"(va) : "l"(barA));
            asm volatile("ld.acquire.gpu.global.b32 %0, [%1];" : "=r"(vb) : "l"(barB));
        } while (va < tA || vb < tB);
    }
    __syncthreads();
}

// lane offsets (bytes) for ldmatrix source addresses
__device__ __forceinline__ uint32_t a_lane_off(int lane) {
    const int am = lane >> 3;
    return (uint32_t)((((am & 1) * 8 + (lane & 7)) * ASTRH) * 2 + (am >> 1) * 16);
}
__device__ __forceinline__ uint32_t b_lane_off(int lane, int wstr) {
    return (uint32_t)(((lane & 7) * wstr) * 2 + ((lane >> 3) & 1) * 16);
}

// issue one A slab (128 rows x 64 halfs) via cp.async: 2 x 16B per thread
__device__ __forceinline__ void a_issue(uint32_t buf_b, const __half* __restrict__ A,
                                        int ldK, int k0, int tid) {
    const int rL = tid >> 3, ch = (tid & 7) * 8;
    cpa16(buf_b + (uint32_t)((rL * ASTRH + ch) * 2),        A + (size_t)rL * ldK + k0 + ch);
    cpa16(buf_b + (uint32_t)(((rL + 64) * ASTRH + ch) * 2), A + (size_t)(rL + 64) * ldK + k0 + ch);
}
// issue one FC B slab (64 rows x 64 halfs): 1 x 16B per thread
__device__ __forceinline__ void b_issue(uint32_t buf_b, const __half* __restrict__ W,
                                        int ldK, int k0, int tid) {
    const int r = tid >> 3, cb = (tid & 7) * 8;
    cpa16(buf_b + (uint32_t)((r * ASTRH + cb) * 2), W + (size_t)r * ldK + k0 + cb);
}

// one PBK=64 k-slab via ldmatrix, full kk (FC path, 4x4 warp grid, R11-proven)
template <int NI>
__device__ __forceinline__ void do_kk4(uint32_t AcB, uint32_t WsB, int wstr,
                                       uint32_t alo, uint32_t blo,
                                       int wm, int wn, float4 (&acc)[2][NI]) {
#pragma unroll
    for (int kk = 0; kk < 4; kk++) {
        uint32_t af[2][4];
#pragma unroll
        for (int mi = 0; mi < 2; mi++) {
            const uint32_t aaddr = AcB + (uint32_t)(((wm * 32 + mi * 16) * ASTRH + kk * 16) * 2) + alo;
            ldsm_x4(af[mi][0], af[mi][1], af[mi][2], af[mi][3], aaddr);
        }
#pragma unroll
        for (int ni = 0; ni < NI; ni++) {
            const uint32_t baddr = WsB + (uint32_t)(((wn * (NI * 8) + ni * 8) * wstr + kk * 16) * 2) + blo;
            uint32_t b0, b1;
            ldsm_x2(b0, b1, baddr);
#pragma unroll
            for (int mi = 0; mi < 2; mi++)
                mma_f16(acc[mi][ni], af[mi][0], af[mi][1], af[mi][2], af[mi][3], b0, b1);
        }
    }
}

// k-split slab: warp handles kk = ks*2 .. ks*2+1 (half the slab k-range).
// Warp grid 4(wm) x 2(wn) x 2(ks); per-warp tile 32 rows x (NI*8) cols.
template <int NI>
__device__ __forceinline__ void do_kk2(uint32_t AcB, uint32_t WsB, int wstr,
                                       uint32_t alo, uint32_t blo,
                                       int wm, int wn, int ks, float4 (&acc)[2][NI]) {
#pragma unroll
    for (int kq = 0; kq < 2; kq++) {
        const int kk = ks * 2 + kq;
        uint32_t af[2][4];
#pragma unroll
        for (int mi = 0; mi < 2; mi++) {
            const uint32_t aaddr = AcB + (uint32_t)(((wm * 32 + mi * 16) * ASTRH + kk * 16) * 2) + alo;
            ldsm_x4(af[mi][0], af[mi][1], af[mi][2], af[mi][3], aaddr);
        }
#pragma unroll
        for (int ni = 0; ni < NI; ni++) {
            const uint32_t baddr = WsB + (uint32_t)(((wn * (NI * 8) + ni * 8) * wstr + kk * 16) * 2) + blo;
            uint32_t b0, b1;
            ldsm_x2(b0, b1, baddr);
#pragma unroll
            for (int mi = 0; mi < 2; mi++)
                mma_f16(acc[mi][ni], af[mi][0], af[mi][1], af[mi][2], af[mi][3], b0, b1);
        }
    }
}

// chain mainloop (R11-proven schedule): NBUF=4 ring, prefetch 3, sync every slab.
template <int NI>
__device__ __forceinline__ void chain_mainloop(int NK, const __half* __restrict__ Abh,
                                               int ldK, uint32_t as_u32, uint32_t ws_u32,
                                               int wstr, uint32_t alo, uint32_t blo,
                                               int wm, int wn, int ks, int tid,
                                               float4 (&acc)[2][NI]) {
#pragma unroll
    for (int s = 0; s < 3; s++) {
        if (s < NK) a_issue(as_u32 + s * ABUF_B, Abh, ldK, s * PBK, tid);
        CP_COMMIT();
    }
    for (int kt = 0; kt < NK; ++kt) {
        CP_WAIT2();
        __syncthreads();
        if (kt + 3 < NK)
            a_issue(as_u32 + ((kt + 3) & (NBUF - 1)) * ABUF_B, Abh, ldK, (kt + 3) * PBK, tid);
        CP_COMMIT();
        do_kk2<NI>(as_u32 + (kt & (NBUF - 1)) * ABUF_B, ws_u32 + kt * PBK * 2, wstr,
                   alo, blo, wm, wn, ks, acc);
    }
    __syncthreads();   // all warps done reading As ring (reused as Cs staging)
}

// ============================================================================
// FC work-steal: logits tile [128 x 64] = hs_t @ fcW^T + fcb (R11-proven path)
// ============================================================================
__device__ void fc_worker(uint32_t smb, const float* __restrict__ fcb,
                          float* __restrict__ out) {
    __shared__ int s_tile;
    const uint32_t bs_u32 = smb;                    // 4 x [64][ASTRH]
    const uint32_t as_u32 = smb + F_ATILE * 2;      // 4 x [128][ASTRH]

    const int tid  = threadIdx.x;
    const int lane = tid & 31;
    const int wid  = tid >> 5;
    const int wm   = wid & 3;
    const int wn   = wid >> 2;
    const uint32_t alo = a_lane_off(lane);
    const uint32_t blo = b_lane_off(lane, ASTRH);

    while (true) {
        __syncthreads();
        if (tid == 0) s_tile = (int)atomicAdd(&g_fc_cnt[0], 1u);
        __syncthreads();
        const int tile = s_tile;
        if (tile >= TSTEPS * 16) return;
        const int t  = tile >> 4;
        const int n0 = (tile & 15) * 64;
        wait_ge(g_bar_lstm, 64u * (unsigned)(t + 1));

        const __half* Abh = g_hsh  + (size_t)t * BB * LL;
        const __half* Wb  = g_fcWh + (size_t)n0 * LL;

        float4 acc[2][2];
#pragma unroll
        for (int mi = 0; mi < 2; mi++)
#pragma unroll
            for (int ni = 0; ni < 2; ni++) acc[mi][ni] = make_float4(0.f, 0.f, 0.f, 0.f);

#pragma unroll
        for (int s = 0; s < 3; s++) {
            a_issue(as_u32 + s * ABUF_B, Abh, LL, s * PBK, tid);
            b_issue(bs_u32 + s * BBUF_B, Wb,  LL, s * PBK, tid);
            CP_COMMIT();
        }
        for (int kt = 0; kt < 16; ++kt) {
            CP_WAIT2();
            __syncthreads();
            if (kt + 3 < 16) {
                const int b = (kt + 3) & (NBUF - 1);
                a_issue(as_u32 + b * ABUF_B, Abh, LL, (kt + 3) * PBK, tid);
                b_issue(bs_u32 + b * BBUF_B, Wb,  LL, (kt + 3) * PBK, tid);
            }
            CP_COMMIT();
            const int c = kt & (NBUF - 1);
            do_kk4<2>(as_u32 + c * ABUF_B, bs_u32 + c * BBUF_B, ASTRH,
                      alo, blo, wm, wn, acc);
        }

#pragma unroll
        for (int mi = 0; mi < 2; mi++) {
#pragma unroll
            for (int ni = 0; ni < 2; ni++) {
                const int r   = wm * 32 + mi * 16 + (lane >> 2);
                const int col = n0 + wn * 16 + ni * 8 + 2 * (lane & 3);
                const float b0 = fcb[col], b1 = fcb[col + 1];
                float* o0 = out + ((size_t)r * TSTEPS + t) * VV + col;
                float* o1 = out + ((size_t)(r + 8) * TSTEPS + t) * VV + col;
                *(float2*)o0 = make_float2(acc[mi][ni].x + b0, acc[mi][ni].y + b1);
                *(float2*)o1 = make_float2(acc[mi][ni].z + b0, acc[mi][ni].w + b1);
            }
        }
    }
}

// ============================================================================
// Fused pipelined kernel, grid = 148 (512 thr = 16 warps/SM):
//   bid 0-31: GRU (64 cols) | bid 32-63: XG (128 cols) | bid 64-127: LSTM (64 cols)
//   bid 128-147: FC steal (chain CTAs join at the end)
// Chains use 4x2x2 (wm x wn x ks) k-split warp tiling.
// ============================================================================
__global__ void __launch_bounds__(NTH)
fused_persist(const float* __restrict__ z, const float* __restrict__ fcb,
              float* __restrict__ out) {
    extern __shared__ __half smh[];
    const uint32_t smb = (uint32_t)__cvta_generic_to_shared(smh);
    const int tid  = threadIdx.x;
    const int lane = tid & 31;
    const int wid  = tid >> 5;
    const int wm   = wid & 3;            // 32-row group
    const int wn2  = (wid >> 2) & 1;     // k-split col group
    const int ks   = wid >> 3;           // k-split half
    const int bid  = blockIdx.x;
    const uint32_t alo = a_lane_off(lane);

    if (bid < 32) {
        // ================= GRU chain: 64 cols (4x2x2 k-split) =================
        __half* Ws = smh;                               // [64][WSTRH_G]
        const uint32_t ws_u32 = smb;
        const uint32_t as_u32 = smb + 64 * WSTRH_G * 2; // 4 x [128][ASTRH]
        float* Cs = (float*)(smh + 64 * WSTRH_G);       // staging, stride CSTR
        const uint32_t blo = b_lane_off(lane, WSTRH_G);
        const int n0 = bid * 64;

        for (int i = tid; i < 64 * 64; i += NTH) {
            const int r = i >> 6, c = (i & 63) * 8;
            *(uint4*)(Ws + r * WSTRH_G + c) = *(const uint4*)(g_Wg1h + (size_t)(n0 + r) * HH + c);
        }
        __syncthreads();

        for (int t = 1; t < TSTEPS; ++t) {
            const __half* Abh  = (t == 1) ? g_zh : g_xh + (size_t)((t - 1) & 1) * BB * HH;
            const float*  hp32 = (t == 1) ? z    : g_x  + (size_t)((t - 1) & 1) * BB * HH;
            float*  xo32 = g_x    + (size_t)(t & 1) * BB * HH;
            __half* xoh  = g_xh   + (size_t)(t & 1) * BB * HH;
            __half* so   = g_seqh + (size_t)t * BB * HH;

            float hp[4];
#pragma unroll
            for (int s = 0; s < 4; s++) {
                const int it = tid + s * NTH;
                hp[s] = hp32[(size_t)(it >> 4) * HH + (n0 >> 2) + (it & 15)];
            }

            float4 acc[2][4];
#pragma unroll
            for (int mi = 0; mi < 2; mi++)
#pragma unroll
                for (int ni = 0; ni < 4; ni++) acc[mi][ni] = make_float4(0.f, 0.f, 0.f, 0.f);

            chain_mainloop<4>(8, Abh, HH, as_u32, ws_u32, WSTRH_G,
                              alo, blo, wm, wn2, ks, tid, acc);

            // staged k-partial reduction: ks0 writes (+bias), ks1 adds
            if (ks == 0) {
#pragma unroll
                for (int mi = 0; mi < 2; mi++) {
#pragma unroll
                    for (int ni = 0; ni < 4; ni++) {
                        const int r = wm * 32 + mi * 16 + (lane >> 2);
                        const int c = wn2 * 32 + ni * 8 + 2 * (lane & 3);
                        const float b0 = g_bg[n0 + c], b1 = g_bg[n0 + c + 1];
                        Cs[r * CSTR + c]           = acc[mi][ni].x + b0;
                        Cs[r * CSTR + c + 1]       = acc[mi][ni].y + b1;
                        Cs[(r + 8) * CSTR + c]     = acc[mi][ni].z + b0;
                        Cs[(r + 8) * CSTR + c + 1] = acc[mi][ni].w + b1;
                    }
                }
            }
            __syncthreads();
            if (ks == 1) {
#pragma unroll
                for (int mi = 0; mi < 2; mi++) {
#pragma unroll
                    for (int ni = 0; ni < 4; ni++) {
                        const int r = wm * 32 + mi * 16 + (lane >> 2);
                        const int c = wn2 * 32 + ni * 8 + 2 * (lane & 3);
                        Cs[r * CSTR + c]           += acc[mi][ni].x;
                        Cs[r * CSTR + c + 1]       += acc[mi][ni].y;
                        Cs[(r + 8) * CSTR + c]     += acc[mi][ni].z;
                        Cs[(r + 8) * CSTR + c + 1] += acc[mi][ni].w;
                    }
                }
            }
            __syncthreads();

#pragma unroll
            for (int s = 0; s < 4; s++) {
                const int it  = tid + s * NTH;
                const int u   = it & 15;
                const int row = it >> 4;
                const int jg  = (n0 >> 2) + u;
                const float4 cv = *(const float4*)(Cs + row * CSTR + 4 * u);
                const float rg = sigf(cv.x);
                const float zg = sigf(cv.y);
                const float nn = tanhf(cv.z + rg * cv.w);
                const float xn = (1.f - zg) * nn + zg * hp[s];
                const int oi = row * HH + jg;
                xo32[oi] = xn;
                xoh[oi]  = __float2half_rn(xn);
                so[oi]   = __float2half_rn(fmaxf(xn, 0.f));
            }

            bar_arrive(g_bar_gru);
            if (t < TSTEPS - 1) {
                wait_ge(g_bar_gru, 32u * (unsigned)t);
                if (t == 1) {
                    for (int i = tid; i < 64 * 64; i += NTH) {
                        const int r = i >> 6, c = (i & 63) * 8;
                        *(uint4*)(Ws + r * WSTRH_G + c) =
                            *(const uint4*)(g_Wgh + (size_t)(n0 + r) * HH + c);
                    }
                    __syncthreads();
                }
            }
        }
        fc_worker(smb, fcb, out);

    } else if (bid < 64) {
        // ================= XG: 128 cols (4x2x2 k-split, NI=8) =================
        __half* Ws = smh;                                // [128][WSTRH_G]
        const uint32_t ws_u32 = smb;
        const uint32_t as_u32 = smb + 128 * WSTRH_G * 2;
        float* Cs = (float*)(smh + 128 * WSTRH_G);       // staging, stride CSTRX
        const uint32_t blo = b_lane_off(lane, WSTRH_G);
        const int n0 = (bid - 32) * 128;

        for (int i = tid; i < 128 * 64; i += NTH) {
            const int r = i >> 6, c = (i & 63) * 8;
            *(uint4*)(Ws + r * WSTRH_G + c) = *(const uint4*)(g_Wihlh + (size_t)(n0 + r) * HH + c);
        }
        __syncthreads();

        for (int t = 1; t < TSTEPS; ++t) {
            wait_ge(g_bar_gru, 32u * (unsigned)t);
            const __half* Abh = g_seqh + (size_t)t * BB * HH;

            float4 acc[2][8];
#pragma unroll
            for (int mi = 0; mi < 2; mi++)
#pragma unroll
                for (int ni = 0; ni < 8; ni++) acc[mi][ni] = make_float4(0.f, 0.f, 0.f, 0.f);

            chain_mainloop<8>(8, Abh, HH, as_u32, ws_u32, WSTRH_G,
                              alo, blo, wm, wn2, ks, tid, acc);

            if (ks == 0) {
#pragma unroll
                for (int mi = 0; mi < 2; mi++) {
#pragma unroll
                    for (int ni = 0; ni < 8; ni++) {
                        const int r = wm * 32 + mi * 16 + (lane >> 2);
                        const int c = wn2 * 64 + ni * 8 + 2 * (lane & 3);
                        Cs[r * CSTRX + c]           = acc[mi][ni].x;
                        Cs[r * CSTRX + c + 1]       = acc[mi][ni].y;
                        Cs[(r + 8) * CSTRX + c]     = acc[mi][ni].z;
                        Cs[(r + 8) * CSTRX + c + 1] = acc[mi][ni].w;
                    }
                }
            }
            __syncthreads();
            if (ks == 1) {
#pragma unroll
                for (int mi = 0; mi < 2; mi++) {
#pragma unroll
                    for (int ni = 0; ni < 8; ni++) {
                        const int r = wm * 32 + mi * 16 + (lane >> 2);
                        const int c = wn2 * 64 + ni * 8 + 2 * (lane & 3);
                        const int col = n0 + c;
                        const float b0 = g_bl[col], b1 = g_bl[col + 1];
                        float* o0 = g_Xg + ((size_t)t * BB + r) * 4096 + col;
                        float* o1 = g_Xg + ((size_t)t * BB + r + 8) * 4096 + col;
                        *(float2*)o0 = make_float2(Cs[r * CSTRX + c] + acc[mi][ni].x + b0,
                                                   Cs[r * CSTRX + c + 1] + acc[mi][ni].y + b1);
                        *(float2*)o1 = make_float2(Cs[(r + 8) * CSTRX + c] + acc[mi][ni].z + b0,
                                                   Cs[(r + 8) * CSTRX + c + 1] + acc[mi][ni].w + b1);
                    }
                }
            }
            bar_arrive(g_bar_xg);
        }
        fc_worker(smb, fcb, out);

    } else if (bid < 128) {
        // ================= LSTM chain: 64 cols (4x2x2 k-split) =================
        __half* Ws = smh;                                // [64][WSTRH_L]
        const uint32_t ws_u32 = smb;
        const uint32_t as_u32 = smb + 64 * WSTRH_L * 2;
        float* Cs = (float*)(smh + 64 * WSTRH_L);        // staging, stride CSTR
        const uint32_t blo = b_lane_off(lane, WSTRH_L);
        const int n0 = (bid - 64) * 64;

        for (int i = tid; i < 64 * 128; i += NTH) {
            const int r = i >> 7, c = (i & 127) * 8;
            *(uint4*)(Ws + r * WSTRH_L + c) = *(const uint4*)(g_Whhlh + (size_t)(n0 + r) * LL + c);
        }
        __syncthreads();

        for (int t = 0; t < TSTEPS; ++t) {
            if (t >= 1)
                wait_ge2(g_bar_xg, 32u * (unsigned)t, g_bar_lstm, 64u * (unsigned)t);

            const __half* Abh = g_hh + (size_t)(t & 1) * BB * LL;
            __half* hoh       = g_hh + (size_t)((t + 1) & 1) * BB * LL;

            float4 xg[4];
            float  cc[4];
#pragma unroll
            for (int s = 0; s < 4; s++) {
                const int it  = tid + s * NTH;
                const int row = it >> 4;
                const int u   = it & 15;
                xg[s] = *(const float4*)(g_Xg + ((size_t)t * BB + row) * 4096 + n0 + 4 * u);
                cc[s] = g_c[row * LL + (n0 >> 2) + u];
            }

            float4 acc[2][4];
#pragma unroll
            for (int mi = 0; mi < 2; mi++)
#pragma unroll
                for (int ni = 0; ni < 4; ni++) acc[mi][ni] = make_float4(0.f, 0.f, 0.f, 0.f);

            if (t >= 1)
                chain_mainloop<4>(16, Abh, LL, as_u32, ws_u32, WSTRH_L,
                                  alo, blo, wm, wn2, ks, tid, acc);

            if (ks == 0) {
#pragma unroll
                for (int mi = 0; mi < 2; mi++) {
#pragma unroll
                    for (int ni = 0; ni < 4; ni++) {
                        const int r = wm * 32 + mi * 16 + (lane >> 2);
                        const int c = wn2 * 32 + ni * 8 + 2 * (lane & 3);
                        Cs[r * CSTR + c]           = acc[mi][ni].x;
                        Cs[r * CSTR + c + 1]       = acc[mi][ni].y;
                        Cs[(r + 8) * CSTR + c]     = acc[mi][ni].z;
                        Cs[(r + 8) * CSTR + c + 1] = acc[mi][ni].w;
                    }
                }
            }
            __syncthreads();
            if (ks == 1) {
#pragma unroll
                for (int mi = 0; mi < 2; mi++) {
#pragma unroll
                    for (int ni = 0; ni < 4; ni++) {
                        const int r = wm * 32 + mi * 16 + (lane >> 2);
                        const int c = wn2 * 32 + ni * 8 + 2 * (lane & 3);
                        Cs[r * CSTR + c]           += acc[mi][ni].x;
                        Cs[r * CSTR + c + 1]       += acc[mi][ni].y;
                        Cs[(r + 8) * CSTR + c]     += acc[mi][ni].z;
                        Cs[(r + 8) * CSTR + c + 1] += acc[mi][ni].w;
                    }
                }
            }
            __syncthreads();

#pragma unroll
            for (int s = 0; s < 4; s++) {
                const int it  = tid + s * NTH;
                const int u   = it & 15;
                const int row = it >> 4;
                const int jg  = (n0 >> 2) + u;
                const float4 cv = *(const float4*)(Cs + row * CSTR + 4 * u);
                const float ig = sigf(cv.x + xg[s].x);
                const float fg = sigf(cv.y + xg[s].y);
                const float gg = tanhf(cv.z + xg[s].z);
                const float og = sigf(cv.w + xg[s].w);
                const int ci = row * LL + jg;
                const float cn = fg * cc[s] + ig * gg;
                g_c[ci] = cn;
                const float hn = og * tanhf(cn);
                hoh[ci] = __float2half_rn(hn);
                g_hsh[((size_t)t * BB + row) * LL + jg] = __float2half_rn(hn);
            }

            bar_arrive(g_bar_lstm);
        }
        fc_worker(smb, fcb, out);

    } else {
        fc_worker(smb, fcb, out);
    }
}

// ---------------- prep kernels ----------------
__global__ void prep_gru(const float* __restrict__ Wih, const float* __restrict__ Whh,
                         const float* __restrict__ bih, const float* __restrict__ bhh) {
    const int idx = blockIdx.x * blockDim.x + threadIdx.x;
    if (idx < 2048 * 512) {
        const int row = idx >> 9, k = idx & 511;
        const int j = row >> 2, g = row & 3;
        float wg, w1;
        if (g == 0)      { wg = Wih[j * 512 + k] + Whh[j * 512 + k];                 w1 = Whh[j * 512 + k]; }
        else if (g == 1) { wg = Wih[(512 + j) * 512 + k] + Whh[(512 + j) * 512 + k]; w1 = Whh[(512 + j) * 512 + k]; }
        else if (g == 2) { wg = Wih[(1024 + j) * 512 + k];                           w1 = 0.f; }
        else             { wg = Whh[(1024 + j) * 512 + k];                           w1 = wg; }
        g_Wgh[idx]  = __float2half_rn(wg);
        g_Wg1h[idx] = __float2half_rn(w1);
    }
    if (idx < 2048) {
        const int j = idx >> 2, g = idx & 3;
        float b;
        if (g == 0)      b = bih[j] + bhh[j];
        else if (g == 1) b = bih[512 + j] + bhh[512 + j];
        else if (g == 2) b = bih[1024 + j];
        else             b = bhh[1024 + j];
        g_bg[idx] = b;
    }
}

__global__ void prep_lstm(const float* __restrict__ Wih, const float* __restrict__ Whh,
                          const float* __restrict__ bih, const float* __restrict__ bhh,
                          const float* __restrict__ fcW) {
    const int idx = blockIdx.x * blockDim.x + threadIdx.x;
    if (idx < 4096 * 1024) {
        const int row = idx >> 10, k = idx & 1023;
        const int j = row >> 2, p = row & 3;
        g_Whhlh[idx] = __float2half_rn(Whh[(size_t)(p * 1024 + j) * 1024 + k]);
    }
    if (idx < 4096 * 512) {
        const int row = idx >> 9, k = idx & 511;
        const int j = row >> 2, p = row & 3;
        g_Wihlh[idx] = __float2half_rn(Wih[(size_t)(p * 1024 + j) * 512 + k]);
    }
    if (idx < 1024 * 1024) {
        g_fcWh[idx] = __float2half_rn(fcW[idx]);
    }
    if (idx < 4096) {
        const int j = idx >> 2, p = idx & 3;
        g_bl[idx] = bih[p * 1024 + j] + bhh[p * 1024 + j];
    }
}

__global__ void prep_zero(const float* __restrict__ z) {
    const int idx = blockIdx.x * blockDim.x + threadIdx.x;
    if (idx < BB * LL) { g_hh[idx] = __float2half_rn(0.f); g_c[idx] = 0.f; }
    if (idx < BB * HH) { g_zh[idx] = __float2half_rn(z[idx]); }
    if (idx < BB * 4096) { g_Xg[idx] = g_bl[idx & 4095]; }
    if (idx == 0) { g_bar_gru[0] = 0u; g_bar_xg[0] = 0u; g_bar_lstm[0] = 0u; g_fc_cnt[0] = 0u; }
}

// ---------------- host launcher ----------------
extern "C" void kernel_launch(void* const* d_in, const int* in_sizes, int n_in,
                              void* d_out, int out_size) {
    const float* z    = (const float*)d_in[0];
    const float* gWih = (const float*)d_in[2];
    const float* gWhh = (const float*)d_in[3];
    const float* gbih = (const float*)d_in[4];
    const float* gbhh = (const float*)d_in[5];
    const float* lWih = (const float*)d_in[6];
    const float* lWhh = (const float*)d_in[7];
    const float* lbih = (const float*)d_in[8];
    const float* lbhh = (const float*)d_in[9];
    const float* fcW  = (const float*)d_in[10];
    const float* fcb  = (const float*)d_in[11];
    float* out = (float*)d_out;

    cudaFuncSetAttribute(fused_persist, cudaFuncAttributeMaxDynamicSharedMemorySize, SMEM_FUSED);

    prep_gru <<<(2048 * 512 + 255) / 256, 256>>>(gWih, gWhh, gbih, gbhh);
    prep_lstm<<<(4096 * 1024 + 255) / 256, 256>>>(lWih, lWhh, lbih, lbhh, fcW);
    prep_zero<<<(BB * 4096 + 255) / 256, 256>>>(z);

    // fused pipeline: GRU | XG | LSTM | FC on disjoint CTA sets.
    // Chains use 4x2x2 k-split warp tiling: smem fragment traffic 96KB -> 64KB
    // per slab, reduced via one extra staging pass.
    fused_persist<<<148, NTH, SMEM_FUSED>>>(z, fcb, out);
}